// round 10
// baseline (speedup 1.0000x reference)
#include <cuda_runtime.h>

#define N_NODES 20000
#define N_EDGES 160000
#define NH 8
#define EPS 1e-12f
#define SLOPE 0.2f

typedef unsigned long long u64;

// ---------------- scratch (zero-initialized at load; k_agg re-zeroes deg/cursor) ----------------
__device__ float g_value[N_NODES * 256];
__device__ float g_scal[N_NODES * 32];   // 0-7 ssrc | 8-15 stgt | 16-23 gate1 | 24-31 q
__device__ float g_B2[256 * 32];
__device__ float g_cq[NH];
__device__ float g_srel_dr[50 * NH];
__device__ float g_srel_da[4 * NH];
__device__ float g_tabmax[2];
__device__ int g_deg[N_NODES];
__device__ int g_cursor[N_NODES];
__device__ int g_off[N_NODES + 1];
__device__ int g_esort[N_EDGES];
__device__ unsigned g_maxraw[2];

__device__ __forceinline__ float leaky(float x) { return x >= 0.f ? x : SLOPE * x; }

__device__ __forceinline__ float wsum(float v) {
#pragma unroll
    for (int o = 16; o; o >>= 1) v += __shfl_xor_sync(0xFFFFFFFFu, v, o);
    return v;
}

__device__ __forceinline__ unsigned encodef(float f) {
    unsigned b = __float_as_uint(f);
    return (b & 0x80000000u) ? ~b : (b | 0x80000000u);
}
__device__ __forceinline__ float decodef(unsigned u) {
    unsigned b = (u & 0x80000000u) ? (u & 0x7FFFFFFFu) : ~u;
    return __uint_as_float(b);
}

__device__ __forceinline__ void ffma2(u64& d, u64 a, u64 b) {
    asm("fma.rn.f32x2 %0, %1, %2, %0;" : "+l"(d) : "l"(a), "l"(b));
}
__device__ __forceinline__ u64 bcast2(float x) {
    u64 r;
    unsigned u = __float_as_uint(x);
    asm("mov.b64 %0, {%1, %2};" : "=l"(r) : "r"(u), "r"(u));
    return r;
}
__device__ __forceinline__ void unpack2(u64 v, float& lo, float& hi) {
    unsigned a, b;
    asm("mov.b64 {%0, %1}, %2;" : "=r"(a), "=r"(b) : "l"(v));
    lo = __uint_as_float(a);
    hi = __uint_as_float(b);
}

// ---------------- pre: tables(b0) | prep(b1..256) | count(b257..881) ----------------
__global__ void __launch_bounds__(256) k_pre(
    const float* __restrict__ Wrel, const float* __restrict__ wrel,
    const float* __restrict__ dre_emb, const float* __restrict__ dae_emb,
    const float* __restrict__ Wv, const float* __restrict__ wsrc,
    const float* __restrict__ wtgt, const float* __restrict__ gatew,
    const float* __restrict__ Wn, const float* __restrict__ nbias,
    const int* __restrict__ ei) {
    int b = blockIdx.x;
    int tid = threadIdx.x;
    if (b == 0) {
        __shared__ float us[NH * 128];
        __shared__ unsigned sm0, sm1;
        if (tid == 0) { sm0 = 0u; sm1 = 0u; }
        if (tid < 2) g_maxraw[tid] = 0u;
        for (int id = tid; id < NH * 128; id += 256) {
            int h = id >> 7, k = id & 127;
            float s = 0.f;
#pragma unroll
            for (int j = 0; j < 16; j++) s += Wrel[k * 128 + h * 16 + j] * wrel[h * 16 + j];
            us[h * 128 + k] = s;
        }
        __syncthreads();
        float mdr = -1e30f, mda = -1e30f;
        for (int id = tid; id < 50 * NH; id += 256) {
            int r = id / NH, h = id % NH;
            float s = 0.f;
            for (int k = 0; k < 64; k++) s += dre_emb[r * 64 + k] * us[h * 128 + k];
            g_srel_dr[r * NH + h] = s;
            mdr = fmaxf(mdr, s);
        }
        for (int id = tid; id < 4 * NH; id += 256) {
            int a = id / NH, h = id % NH;
            float s = 0.f;
            for (int k = 0; k < 64; k++) s += dae_emb[a * 64 + k] * us[h * 128 + 64 + k];
            g_srel_da[a * NH + h] = s;
            mda = fmaxf(mda, s);
        }
        atomicMax(&sm0, encodef(mdr));
        atomicMax(&sm1, encodef(mda));
        __syncthreads();
        if (tid == 0) {
            g_tabmax[0] = decodef(sm0);
            g_tabmax[1] = decodef(sm1);
        }
    } else if (b <= 256) {
        int k = b - 1;
        int lane = tid & 31, h = tid >> 5;
        float v = Wv[k * 256 + h * 32 + lane];
        float s1 = wsum(v * wsrc[h * 32 + lane]);
        float s2 = wsum(v * wtgt[h * 32 + lane]);
        float s3p = 0.f;
#pragma unroll
        for (int j = 0; j < 8; j++) {
            int t = j * 32 + lane;
            s3p += Wn[k * 256 + t] * gatew[(256 + t) * 8 + h];
        }
        float s3 = wsum(s3p);
        if (lane == 0) {
            g_B2[k * 32 + h] = s1;
            g_B2[k * 32 + 8 + h] = s2;
            g_B2[k * 32 + 16 + h] = gatew[k * 8 + h];
            g_B2[k * 32 + 24 + h] = s3;
        }
        if (k == 0) {
            float cp = 0.f;
#pragma unroll
            for (int j = 0; j < 8; j++) {
                int t = j * 32 + lane;
                cp += nbias[t] * gatew[(256 + t) * 8 + h];
            }
            float c = wsum(cp);
            if (lane == 0) g_cq[h] = c;
        }
    } else {
        int e = (b - 257) * 256 + tid;
        if (e < N_EDGES) atomicAdd(&g_deg[ei[N_EDGES + e]], 1);
    }
}

// ---------------- scan: 1 block, thread-local 20 elems + warp/block scan ----------------
__global__ void __launch_bounds__(1024) k_scan() {
    __shared__ int wsums[32];
    int tid = threadIdx.x, lane = tid & 31, wid = tid >> 5;
    int base = tid * 20;
    int v[20];
    int s = 0;
#pragma unroll
    for (int j = 0; j < 20; j++) {
        int i = base + j;
        v[j] = (i < N_NODES) ? g_deg[i] : 0;
        s += v[j];
    }
    int x = s;
#pragma unroll
    for (int o = 1; o < 32; o <<= 1) {
        int t = __shfl_up_sync(0xFFFFFFFFu, x, o);
        if (lane >= o) x += t;
    }
    if (lane == 31) wsums[wid] = x;
    __syncthreads();
    if (wid == 0) {
        int ws = wsums[lane];
#pragma unroll
        for (int o = 1; o < 32; o <<= 1) {
            int t = __shfl_up_sync(0xFFFFFFFFu, ws, o);
            if (lane >= o) ws += t;
        }
        wsums[lane] = ws;
    }
    __syncthreads();
    int run = (wid ? wsums[wid - 1] : 0) + x - s;
#pragma unroll
    for (int j = 0; j < 20; j++) {
        int i = base + j;
        if (i < N_NODES) g_off[i] = run;
        run += v[j];
    }
    if (tid == 1023) g_off[N_NODES] = run;
}

// ---------------- fused GEMM (FFMA2, 64-wide tiles) + nodemax + CSR fill ----------------
#define BM 128
#define BN 64
#define BK 16
#define ASTR 132
#define BSTR 68

__global__ void __launch_bounds__(256) k_gemm(const float* __restrict__ inp,
                                              const float* __restrict__ Wv,
                                              const int* __restrict__ ei,
                                              const int* __restrict__ dre,
                                              const int* __restrict__ dae) {
    __shared__ float As[2][BK][ASTR];
    __shared__ float Bs[2][BK][BSTR];
    int tid = threadIdx.x;
    int bx = blockIdx.x, by = blockIdx.y;

    if (bx == 5) {
        int stride = gridDim.y * 256;
        for (int e = by * 256 + tid; e < N_EDGES; e += stride) {
            int src = ei[e], tgt = ei[N_EDGES + e];
            int pos = g_off[tgt] + atomicAdd(&g_cursor[tgt], 1);
            g_esort[pos] = src | (dre[e] << 16) | (dae[e] << 22);
        }
        return;
    }

    int row0 = by * BM;
    bool scal = (bx == 4);
    int col0 = bx * BN;

    int am = tid >> 2, ak = (tid & 3) << 2;
    int bk = tid >> 4, bc = (tid & 15) << 2;
    int tx = tid & 15, ty = tid >> 4;

    u64 acc2[4][4];
#pragma unroll
    for (int i = 0; i < 4; i++)
#pragma unroll
        for (int j = 0; j < 4; j++) acc2[i][j] = 0ull;

    int r0i = row0 + am, r1i = row0 + am + 64;
    bool v0 = r0i < N_NODES, v1 = r1i < N_NODES;
    float4 ra0, ra1, rb;
    const float4 z4 = make_float4(0.f, 0.f, 0.f, 0.f);

    ra0 = v0 ? *(const float4*)(inp + (size_t)r0i * 256 + ak) : z4;
    ra1 = v1 ? *(const float4*)(inp + (size_t)r1i * 256 + ak) : z4;
    if (!scal) rb = *(const float4*)(Wv + (size_t)bk * 256 + col0 + bc);
    else rb = (bc < 32) ? *(const float4*)(g_B2 + bk * 32 + bc) : z4;

    As[0][ak + 0][am] = ra0.x; As[0][ak + 1][am] = ra0.y;
    As[0][ak + 2][am] = ra0.z; As[0][ak + 3][am] = ra0.w;
    As[0][ak + 0][am + 64] = ra1.x; As[0][ak + 1][am + 64] = ra1.y;
    As[0][ak + 2][am + 64] = ra1.z; As[0][ak + 3][am + 64] = ra1.w;
    *(float4*)&Bs[0][bk][bc] = rb;
    __syncthreads();

    for (int t = 0; t < 16; t++) {
        int buf = t & 1;
        if (t < 15) {
            int k0 = (t + 1) * BK;
            ra0 = v0 ? *(const float4*)(inp + (size_t)r0i * 256 + k0 + ak) : z4;
            ra1 = v1 ? *(const float4*)(inp + (size_t)r1i * 256 + k0 + ak) : z4;
            if (!scal) rb = *(const float4*)(Wv + (size_t)(k0 + bk) * 256 + col0 + bc);
            else rb = (bc < 32) ? *(const float4*)(g_B2 + (k0 + bk) * 32 + bc) : z4;
        }
#pragma unroll
        for (int kk = 0; kk < BK; kk++) {
            const float* abase = &As[buf][kk][ty * 8];
            u64 a01 = *(const u64*)(abase + 0);
            u64 a23 = *(const u64*)(abase + 2);
            u64 a45 = *(const u64*)(abase + 4);
            u64 a67 = *(const u64*)(abase + 6);
            float4 b4 = *(const float4*)&Bs[buf][kk][tx * 4];
            u64 bb0 = bcast2(b4.x), bb1 = bcast2(b4.y), bb2 = bcast2(b4.z), bb3 = bcast2(b4.w);
            ffma2(acc2[0][0], a01, bb0); ffma2(acc2[0][1], a01, bb1);
            ffma2(acc2[0][2], a01, bb2); ffma2(acc2[0][3], a01, bb3);
            ffma2(acc2[1][0], a23, bb0); ffma2(acc2[1][1], a23, bb1);
            ffma2(acc2[1][2], a23, bb2); ffma2(acc2[1][3], a23, bb3);
            ffma2(acc2[2][0], a45, bb0); ffma2(acc2[2][1], a45, bb1);
            ffma2(acc2[2][2], a45, bb2); ffma2(acc2[2][3], a45, bb3);
            ffma2(acc2[3][0], a67, bb0); ffma2(acc2[3][1], a67, bb1);
            ffma2(acc2[3][2], a67, bb2); ffma2(acc2[3][3], a67, bb3);
        }
        if (t < 15) {
            int nb = buf ^ 1;
            As[nb][ak + 0][am] = ra0.x; As[nb][ak + 1][am] = ra0.y;
            As[nb][ak + 2][am] = ra0.z; As[nb][ak + 3][am] = ra0.w;
            As[nb][ak + 0][am + 64] = ra1.x; As[nb][ak + 1][am + 64] = ra1.y;
            As[nb][ak + 2][am + 64] = ra1.z; As[nb][ak + 3][am + 64] = ra1.w;
            *(float4*)&Bs[nb][bk][bc] = rb;
            __syncthreads();
        }
    }

    float mssrc = -1e30f, mstgt = -1e30f;
#pragma unroll
    for (int i2 = 0; i2 < 4; i2++) {
        float lo0, hi0, lo1, hi1, lo2, hi2, lo3, hi3;
        unpack2(acc2[i2][0], lo0, hi0);
        unpack2(acc2[i2][1], lo1, hi1);
        unpack2(acc2[i2][2], lo2, hi2);
        unpack2(acc2[i2][3], lo3, hi3);
        int rlo = row0 + ty * 8 + 2 * i2;
        int rhi = rlo + 1;
        if (!scal) {
            if (rlo < N_NODES)
                *(float4*)(g_value + (size_t)rlo * 256 + col0 + tx * 4) =
                    make_float4(lo0, lo1, lo2, lo3);
            if (rhi < N_NODES)
                *(float4*)(g_value + (size_t)rhi * 256 + col0 + tx * 4) =
                    make_float4(hi0, hi1, hi2, hi3);
        } else if (tx < 8) {
            if (rlo < N_NODES)
                *(float4*)(g_scal + (size_t)rlo * 32 + tx * 4) = make_float4(lo0, lo1, lo2, lo3);
            if (rhi < N_NODES)
                *(float4*)(g_scal + (size_t)rhi * 32 + tx * 4) = make_float4(hi0, hi1, hi2, hi3);
            if (tx < 2) {
                if (rlo < N_NODES) mssrc = fmaxf(mssrc, fmaxf(fmaxf(lo0, lo1), fmaxf(lo2, lo3)));
                if (rhi < N_NODES) mssrc = fmaxf(mssrc, fmaxf(fmaxf(hi0, hi1), fmaxf(hi2, hi3)));
            } else if (tx < 4) {
                if (rlo < N_NODES) mstgt = fmaxf(mstgt, fmaxf(fmaxf(lo0, lo1), fmaxf(lo2, lo3)));
                if (rhi < N_NODES) mstgt = fmaxf(mstgt, fmaxf(fmaxf(hi0, hi1), fmaxf(hi2, hi3)));
            }
        }
    }
    if (scal) {
#pragma unroll
        for (int o = 16; o; o >>= 1) {
            mssrc = fmaxf(mssrc, __shfl_xor_sync(0xFFFFFFFFu, mssrc, o));
            mstgt = fmaxf(mstgt, __shfl_xor_sync(0xFFFFFFFFu, mstgt, o));
        }
        if ((tid & 31) == 0) {
            atomicMax(&g_maxraw[0], encodef(mssrc));
            atomicMax(&g_maxraw[1], encodef(mstgt));
        }
    }
}

// ---------------- fused agg: 4 nodes/block, 2 warps per node's edges, epilogue warp=head ----------------
__global__ void __launch_bounds__(256, 3) k_agg(const float* __restrict__ fpw,
                                                const float* __restrict__ fpb,
                                                const float* __restrict__ gateb,
                                                const float* __restrict__ fbias,
                                                float* __restrict__ out) {
    __shared__ float tdr[50 * NH];
    __shared__ float tda[4 * NH];
    __shared__ float part[8][516];    // [warp][h*64 + d]  unnormalized av(d<32)/ar(d>=32)
    __shared__ float pden[8][16];     // [warp][h] = denv, [warp][8+h] = denr
    __shared__ float pq[8][8];
    __shared__ float inv_s[4][16];    // [node][h] = idv, [node][8+h] = idr
    __shared__ float gate_s[4][8];
    __shared__ int deg_s[4];
    int tid = threadIdx.x, lane = tid & 31, w = tid >> 5;
    for (int i = tid; i < 50 * NH; i += 256) tdr[i] = g_srel_dr[i];
    if (tid < 32) tda[tid] = g_srel_da[tid];

    int nn = w >> 1, half = w & 1;
    int nbase = blockIdx.x * 4;
    int n = nbase + nn;
    float maxssrc = decodef(g_maxraw[0]);
    float maxstgt = decodef(g_maxraw[1]);
    float Mv = leaky(maxssrc + maxstgt);
    float Mr = leaky(g_tabmax[0] + g_tabmax[1] + maxstgt);

    int h = lane >> 2;
    int q4 = lane & 3;
    int E0 = g_off[n], E1 = g_off[n + 1];
    int cnt = E1 - E0;
    int cnt0 = (cnt + 1) >> 1;
    int e0 = half ? E0 + cnt0 : E0;
    int e1 = half ? E1 : E0 + cnt0;
    float stgt = g_scal[n * 32 + 8 + h];
    __syncthreads();  // tdr/tda ready

    u64 accv2[4], accr2[4];
#pragma unroll
    for (int j = 0; j < 4; j++) { accv2[j] = 0ull; accr2[j] = 0ull; }
    float denv = 0.f, denr = 0.f, accq = 0.f;

    const float* vbase = g_value + h * 32 + q4 * 8;

    int pk = 0;
    float sv = 0.f, qv = 0.f;
    ulonglong2 X0, X1;
    if (e0 < e1) {
        pk = g_esort[e0];
        int src = pk & 0xFFFF;
        sv = g_scal[src * 32 + h];
        qv = g_scal[src * 32 + 24 + h];
        X0 = *(const ulonglong2*)(vbase + (size_t)src * 256);
        X1 = *(const ulonglong2*)(vbase + (size_t)src * 256 + 4);
    }
    for (int p = e0; p < e1; p++) {
        int pkn = (p + 1 < e1) ? g_esort[p + 1] : pk;
        int srcn = pkn & 0xFFFF;
        float svn = g_scal[srcn * 32 + h];
        float qvn = g_scal[srcn * 32 + 24 + h];
        ulonglong2 X0n = *(const ulonglong2*)(vbase + (size_t)srcn * 256);
        ulonglong2 X1n = *(const ulonglong2*)(vbase + (size_t)srcn * 256 + 4);

        int dr = (pk >> 16) & 0x3F;
        int da = (pk >> 22) & 0x3;
        float ev = __expf(leaky(sv + stgt) - Mv);
        float er = __expf(leaky(tdr[dr * 8 + h] + tda[da * 8 + h] + stgt) - Mr);
        denv += ev;
        denr += er;
        accq += qv;
        u64 ev2 = bcast2(ev), er2 = bcast2(er);
        ffma2(accv2[0], X0.x, ev2); ffma2(accv2[1], X0.y, ev2);
        ffma2(accv2[2], X1.x, ev2); ffma2(accv2[3], X1.y, ev2);
        ffma2(accr2[0], X0.x, er2); ffma2(accr2[1], X0.y, er2);
        ffma2(accr2[2], X1.x, er2); ffma2(accr2[3], X1.y, er2);

        pk = pkn; sv = svn; qv = qvn; X0 = X0n; X1 = X1n;
    }

    // write partials (unnormalized)
    {
        float f0, f1, f2, f3, f4, f5, f6, f7;
        unpack2(accv2[0], f0, f1); unpack2(accv2[1], f2, f3);
        unpack2(accv2[2], f4, f5); unpack2(accv2[3], f6, f7);
        *(float4*)&part[w][h * 64 + q4 * 8] = make_float4(f0, f1, f2, f3);
        *(float4*)&part[w][h * 64 + q4 * 8 + 4] = make_float4(f4, f5, f6, f7);
        unpack2(accr2[0], f0, f1); unpack2(accr2[1], f2, f3);
        unpack2(accr2[2], f4, f5); unpack2(accr2[3], f6, f7);
        *(float4*)&part[w][h * 64 + 32 + q4 * 8] = make_float4(f0, f1, f2, f3);
        *(float4*)&part[w][h * 64 + 32 + q4 * 8 + 4] = make_float4(f4, f5, f6, f7);
    }
    if (q4 == 0) {
        pden[w][h] = denv;
        pden[w][8 + h] = denr;
        pq[w][h] = accq;
        if (h == 0 && half == 0) deg_s[nn] = cnt;
    }
    __syncthreads();

    // combine denominators + gate (32 threads: node n2, head hh2)
    if (tid < 32) {
        int n2 = tid >> 3, hh2 = tid & 7;
        int wA = n2 * 2, wB = n2 * 2 + 1;
        float dv = pden[wA][hh2] + pden[wB][hh2] + EPS;
        float drr = pden[wA][8 + hh2] + pden[wB][8 + hh2] + EPS;
        inv_s[n2][hh2] = 1.f / dv;
        inv_s[n2][8 + hh2] = 1.f / drr;
        float aq = pq[wA][hh2] + pq[wB][hh2];
        int dg = deg_s[n2];
        float g1 = g_scal[(nbase + n2) * 32 + 16 + hh2];
        float nbterm = dg > 0 ? aq / (float)dg + g_cq[hh2] : 0.f;
        gate_s[n2][hh2] = 1.f / (1.f + __expf(-(g1 + nbterm + gateb[hh2])));
    }
    __syncthreads();

    // epilogue: warp w == head hh, 4 nodes
    int hh = w;
    float ho[4];
    float bias = fpb[hh * 32 + lane];
#pragma unroll
    for (int k = 0; k < 4; k++) ho[k] = bias;
#pragma unroll
    for (int half2 = 0; half2 < 2; half2++) {
        float wreg[32];
#pragma unroll
        for (int d = 0; d < 32; d++) wreg[d] = fpw[hh * 2048 + (half2 * 32 + d) * 32 + lane];
#pragma unroll
        for (int k = 0; k < 4; k++) {
            int wA = k * 2, wB = k * 2 + 1;
            float s = 0.f;
#pragma unroll
            for (int d4 = 0; d4 < 8; d4++) {
                float4 A = *(const float4*)&part[wA][hh * 64 + half2 * 32 + d4 * 4];
                float4 B = *(const float4*)&part[wB][hh * 64 + half2 * 32 + d4 * 4];
                s += (A.x + B.x) * wreg[d4 * 4 + 0] + (A.y + B.y) * wreg[d4 * 4 + 1] +
                     (A.z + B.z) * wreg[d4 * 4 + 2] + (A.w + B.w) * wreg[d4 * 4 + 3];
            }
            ho[k] += s * inv_s[k][half2 * 8 + hh];
        }
    }
    float fb = fbias[hh * 32 + lane];
#pragma unroll
    for (int k = 0; k < 4; k++) {
        out[(size_t)(nbase + k) * 256 + hh * 32 + lane] = ho[k] * gate_s[k][hh] + fb;
    }

    // re-zero CSR state for the next call
    if (tid < 4) {
        g_deg[nbase + tid] = 0;
        g_cursor[nbase + tid] = 0;
    }
}

// ---------------- launcher ----------------
extern "C" void kernel_launch(void* const* d_in, const int* in_sizes, int n_in,
                              void* d_out, int out_size) {
    const float* inp = (const float*)d_in[0];
    const float* Wv = (const float*)d_in[2];
    const float* Wrel = (const float*)d_in[3];
    const float* dre_emb = (const float*)d_in[4];
    const float* dae_emb = (const float*)d_in[5];
    const float* wsrc = (const float*)d_in[6];
    const float* wtgt = (const float*)d_in[7];
    const float* wrel = (const float*)d_in[8];
    const float* fpw = (const float*)d_in[9];
    const float* fpb = (const float*)d_in[10];
    const float* Wn = (const float*)d_in[11];
    const float* nbias = (const float*)d_in[12];
    const float* gatew = (const float*)d_in[13];
    const float* gateb = (const float*)d_in[14];
    const float* fbias = (const float*)d_in[15];
    const int* ei = (const int*)d_in[16];
    const int* dre = (const int*)d_in[17];
    const int* dae = (const int*)d_in[18];
    float* out = (float*)d_out;

    k_pre<<<882, 256>>>(Wrel, wrel, dre_emb, dae_emb, Wv, wsrc, wtgt, gatew,
                        Wn, nbias, ei);                                              // 1
    k_scan<<<1, 1024>>>();                                                           // 2
    k_gemm<<<dim3(6, (N_NODES + BM - 1) / BM), 256>>>(inp, Wv, ei, dre, dae);        // 3
    k_agg<<<N_NODES / 4, 256>>>(fpw, fpb, gateb, fbias, out);                        // 4 (profiled)
}

// round 11
// speedup vs baseline: 1.2126x; 1.2126x over previous
#include <cuda_runtime.h>

#define N_NODES 20000
#define N_EDGES 160000
#define NH 8
#define EPS 1e-12f
#define SLOPE 0.2f

typedef unsigned long long u64;

// ---------------- scratch (zero-initialized at load; k_agg re-zeroes deg/cursor) ----------------
__device__ float g_value[N_NODES * 256];
// g_scal layout: col 2h = ssrc_h, col 2h+1 = q_h (h=0..7), col 16+h = stgt_h, col 24+h = gate1_h
__device__ float g_scal[N_NODES * 32];
__device__ float g_B2[256 * 32];
__device__ float g_cq[NH];
__device__ float g_srel_dr[50 * NH];
__device__ float g_srel_da[4 * NH];
__device__ float g_tabmax[2];
__device__ int g_deg[N_NODES];
__device__ int g_cursor[N_NODES];
__device__ int g_off[N_NODES + 1];
__device__ int g_esort[N_EDGES];
__device__ unsigned g_maxraw[2];

__device__ __forceinline__ float leaky(float x) { return x >= 0.f ? x : SLOPE * x; }

__device__ __forceinline__ float wsum(float v) {
#pragma unroll
    for (int o = 16; o; o >>= 1) v += __shfl_xor_sync(0xFFFFFFFFu, v, o);
    return v;
}

__device__ __forceinline__ unsigned encodef(float f) {
    unsigned b = __float_as_uint(f);
    return (b & 0x80000000u) ? ~b : (b | 0x80000000u);
}
__device__ __forceinline__ float decodef(unsigned u) {
    unsigned b = (u & 0x80000000u) ? (u & 0x7FFFFFFFu) : ~u;
    return __uint_as_float(b);
}

__device__ __forceinline__ void ffma2(u64& d, u64 a, u64 b) {
    asm("fma.rn.f32x2 %0, %1, %2, %0;" : "+l"(d) : "l"(a), "l"(b));
}
__device__ __forceinline__ u64 bcast2(float x) {
    u64 r;
    unsigned u = __float_as_uint(x);
    asm("mov.b64 %0, {%1, %2};" : "=l"(r) : "r"(u), "r"(u));
    return r;
}
__device__ __forceinline__ void unpack2(u64 v, float& lo, float& hi) {
    unsigned a, b;
    asm("mov.b64 {%0, %1}, %2;" : "=r"(a), "=r"(b) : "l"(v));
    lo = __uint_as_float(a);
    hi = __uint_as_float(b);
}

// ---------------- pre: tables(b0) | prep(b1..256) | count(b257..881) ----------------
__global__ void __launch_bounds__(256) k_pre(
    const float* __restrict__ Wrel, const float* __restrict__ wrel,
    const float* __restrict__ dre_emb, const float* __restrict__ dae_emb,
    const float* __restrict__ Wv, const float* __restrict__ wsrc,
    const float* __restrict__ wtgt, const float* __restrict__ gatew,
    const float* __restrict__ Wn, const float* __restrict__ nbias,
    const int* __restrict__ ei) {
    int b = blockIdx.x;
    int tid = threadIdx.x;
    if (b == 0) {
        __shared__ float us[NH * 128];
        __shared__ unsigned sm0, sm1;
        if (tid == 0) { sm0 = 0u; sm1 = 0u; }
        if (tid < 2) g_maxraw[tid] = 0u;
        for (int id = tid; id < NH * 128; id += 256) {
            int h = id >> 7, k = id & 127;
            float s = 0.f;
#pragma unroll
            for (int j = 0; j < 16; j++) s += Wrel[k * 128 + h * 16 + j] * wrel[h * 16 + j];
            us[h * 128 + k] = s;
        }
        __syncthreads();
        float mdr = -1e30f, mda = -1e30f;
        for (int id = tid; id < 50 * NH; id += 256) {
            int r = id / NH, h = id % NH;
            float s = 0.f;
            for (int k = 0; k < 64; k++) s += dre_emb[r * 64 + k] * us[h * 128 + k];
            g_srel_dr[r * NH + h] = s;
            mdr = fmaxf(mdr, s);
        }
        for (int id = tid; id < 4 * NH; id += 256) {
            int a = id / NH, h = id % NH;
            float s = 0.f;
            for (int k = 0; k < 64; k++) s += dae_emb[a * 64 + k] * us[h * 128 + 64 + k];
            g_srel_da[a * NH + h] = s;
            mda = fmaxf(mda, s);
        }
        atomicMax(&sm0, encodef(mdr));
        atomicMax(&sm1, encodef(mda));
        __syncthreads();
        if (tid == 0) {
            g_tabmax[0] = decodef(sm0);
            g_tabmax[1] = decodef(sm1);
        }
    } else if (b <= 256) {
        int k = b - 1;
        int lane = tid & 31, h = tid >> 5;
        float v = Wv[k * 256 + h * 32 + lane];
        float s1 = wsum(v * wsrc[h * 32 + lane]);
        float s2 = wsum(v * wtgt[h * 32 + lane]);
        float s3p = 0.f;
#pragma unroll
        for (int j = 0; j < 8; j++) {
            int t = j * 32 + lane;
            s3p += Wn[k * 256 + t] * gatew[(256 + t) * 8 + h];
        }
        float s3 = wsum(s3p);
        if (lane == 0) {
            g_B2[k * 32 + 2 * h] = s1;        // ssrc_h
            g_B2[k * 32 + 2 * h + 1] = s3;    // q_h
            g_B2[k * 32 + 16 + h] = s2;       // stgt_h
            g_B2[k * 32 + 24 + h] = gatew[k * 8 + h];  // gate1_h
        }
        if (k == 0) {
            float cp = 0.f;
#pragma unroll
            for (int j = 0; j < 8; j++) {
                int t = j * 32 + lane;
                cp += nbias[t] * gatew[(256 + t) * 8 + h];
            }
            float c = wsum(cp);
            if (lane == 0) g_cq[h] = c;
        }
    } else {
        int e = (b - 257) * 256 + tid;
        if (e < N_EDGES) atomicAdd(&g_deg[ei[N_EDGES + e]], 1);
    }
}

// ---------------- scan: 1 block, thread-local 20 elems + warp/block scan ----------------
__global__ void __launch_bounds__(1024) k_scan() {
    __shared__ int wsums[32];
    int tid = threadIdx.x, lane = tid & 31, wid = tid >> 5;
    int base = tid * 20;
    int v[20];
    int s = 0;
#pragma unroll
    for (int j = 0; j < 20; j++) {
        int i = base + j;
        v[j] = (i < N_NODES) ? g_deg[i] : 0;
        s += v[j];
    }
    int x = s;
#pragma unroll
    for (int o = 1; o < 32; o <<= 1) {
        int t = __shfl_up_sync(0xFFFFFFFFu, x, o);
        if (lane >= o) x += t;
    }
    if (lane == 31) wsums[wid] = x;
    __syncthreads();
    if (wid == 0) {
        int ws = wsums[lane];
#pragma unroll
        for (int o = 1; o < 32; o <<= 1) {
            int t = __shfl_up_sync(0xFFFFFFFFu, ws, o);
            if (lane >= o) ws += t;
        }
        wsums[lane] = ws;
    }
    __syncthreads();
    int run = (wid ? wsums[wid - 1] : 0) + x - s;
#pragma unroll
    for (int j = 0; j < 20; j++) {
        int i = base + j;
        if (i < N_NODES) g_off[i] = run;
        run += v[j];
    }
    if (tid == 1023) g_off[N_NODES] = run;
}

// ---------------- fused GEMM (FFMA2, 64-wide tiles) + nodemax + CSR fill ----------------
#define BM 128
#define BN 64
#define BK 16
#define ASTR 132
#define BSTR 68

__global__ void __launch_bounds__(256) k_gemm(const float* __restrict__ inp,
                                              const float* __restrict__ Wv,
                                              const int* __restrict__ ei,
                                              const int* __restrict__ dre,
                                              const int* __restrict__ dae) {
    __shared__ float As[2][BK][ASTR];
    __shared__ float Bs[2][BK][BSTR];
    int tid = threadIdx.x;
    int bx = blockIdx.x, by = blockIdx.y;

    if (bx == 5) {
        int stride = gridDim.y * 256;
        for (int e = by * 256 + tid; e < N_EDGES; e += stride) {
            int src = ei[e], tgt = ei[N_EDGES + e];
            int pos = g_off[tgt] + atomicAdd(&g_cursor[tgt], 1);
            g_esort[pos] = src | (dre[e] << 16) | (dae[e] << 22);
        }
        return;
    }

    int row0 = by * BM;
    bool scal = (bx == 4);
    int col0 = bx * BN;

    int am = tid >> 2, ak = (tid & 3) << 2;
    int bk = tid >> 4, bc = (tid & 15) << 2;
    int tx = tid & 15, ty = tid >> 4;

    u64 acc2[4][4];
#pragma unroll
    for (int i = 0; i < 4; i++)
#pragma unroll
        for (int j = 0; j < 4; j++) acc2[i][j] = 0ull;

    int r0i = row0 + am, r1i = row0 + am + 64;
    bool v0 = r0i < N_NODES, v1 = r1i < N_NODES;
    float4 ra0, ra1, rb;
    const float4 z4 = make_float4(0.f, 0.f, 0.f, 0.f);

    ra0 = v0 ? *(const float4*)(inp + (size_t)r0i * 256 + ak) : z4;
    ra1 = v1 ? *(const float4*)(inp + (size_t)r1i * 256 + ak) : z4;
    if (!scal) rb = *(const float4*)(Wv + (size_t)bk * 256 + col0 + bc);
    else rb = (bc < 32) ? *(const float4*)(g_B2 + bk * 32 + bc) : z4;

    As[0][ak + 0][am] = ra0.x; As[0][ak + 1][am] = ra0.y;
    As[0][ak + 2][am] = ra0.z; As[0][ak + 3][am] = ra0.w;
    As[0][ak + 0][am + 64] = ra1.x; As[0][ak + 1][am + 64] = ra1.y;
    As[0][ak + 2][am + 64] = ra1.z; As[0][ak + 3][am + 64] = ra1.w;
    *(float4*)&Bs[0][bk][bc] = rb;
    __syncthreads();

    for (int t = 0; t < 16; t++) {
        int buf = t & 1;
        if (t < 15) {
            int k0 = (t + 1) * BK;
            ra0 = v0 ? *(const float4*)(inp + (size_t)r0i * 256 + k0 + ak) : z4;
            ra1 = v1 ? *(const float4*)(inp + (size_t)r1i * 256 + k0 + ak) : z4;
            if (!scal) rb = *(const float4*)(Wv + (size_t)(k0 + bk) * 256 + col0 + bc);
            else rb = (bc < 32) ? *(const float4*)(g_B2 + (k0 + bk) * 32 + bc) : z4;
        }
#pragma unroll
        for (int kk = 0; kk < BK; kk++) {
            const float* abase = &As[buf][kk][ty * 8];
            u64 a01 = *(const u64*)(abase + 0);
            u64 a23 = *(const u64*)(abase + 2);
            u64 a45 = *(const u64*)(abase + 4);
            u64 a67 = *(const u64*)(abase + 6);
            float4 b4 = *(const float4*)&Bs[buf][kk][tx * 4];
            u64 bb0 = bcast2(b4.x), bb1 = bcast2(b4.y), bb2 = bcast2(b4.z), bb3 = bcast2(b4.w);
            ffma2(acc2[0][0], a01, bb0); ffma2(acc2[0][1], a01, bb1);
            ffma2(acc2[0][2], a01, bb2); ffma2(acc2[0][3], a01, bb3);
            ffma2(acc2[1][0], a23, bb0); ffma2(acc2[1][1], a23, bb1);
            ffma2(acc2[1][2], a23, bb2); ffma2(acc2[1][3], a23, bb3);
            ffma2(acc2[2][0], a45, bb0); ffma2(acc2[2][1], a45, bb1);
            ffma2(acc2[2][2], a45, bb2); ffma2(acc2[2][3], a45, bb3);
            ffma2(acc2[3][0], a67, bb0); ffma2(acc2[3][1], a67, bb1);
            ffma2(acc2[3][2], a67, bb2); ffma2(acc2[3][3], a67, bb3);
        }
        if (t < 15) {
            int nb = buf ^ 1;
            As[nb][ak + 0][am] = ra0.x; As[nb][ak + 1][am] = ra0.y;
            As[nb][ak + 2][am] = ra0.z; As[nb][ak + 3][am] = ra0.w;
            As[nb][ak + 0][am + 64] = ra1.x; As[nb][ak + 1][am + 64] = ra1.y;
            As[nb][ak + 2][am + 64] = ra1.z; As[nb][ak + 3][am + 64] = ra1.w;
            *(float4*)&Bs[nb][bk][bc] = rb;
            __syncthreads();
        }
    }

    float mssrc = -1e30f, mstgt = -1e30f;
#pragma unroll
    for (int i2 = 0; i2 < 4; i2++) {
        float lo0, hi0, lo1, hi1, lo2, hi2, lo3, hi3;
        unpack2(acc2[i2][0], lo0, hi0);
        unpack2(acc2[i2][1], lo1, hi1);
        unpack2(acc2[i2][2], lo2, hi2);
        unpack2(acc2[i2][3], lo3, hi3);
        int rlo = row0 + ty * 8 + 2 * i2;
        int rhi = rlo + 1;
        if (!scal) {
            if (rlo < N_NODES)
                *(float4*)(g_value + (size_t)rlo * 256 + col0 + tx * 4) =
                    make_float4(lo0, lo1, lo2, lo3);
            if (rhi < N_NODES)
                *(float4*)(g_value + (size_t)rhi * 256 + col0 + tx * 4) =
                    make_float4(hi0, hi1, hi2, hi3);
        } else if (tx < 8) {
            if (rlo < N_NODES)
                *(float4*)(g_scal + (size_t)rlo * 32 + tx * 4) = make_float4(lo0, lo1, lo2, lo3);
            if (rhi < N_NODES)
                *(float4*)(g_scal + (size_t)rhi * 32 + tx * 4) = make_float4(hi0, hi1, hi2, hi3);
            // new layout: ssrc at even cols 0..15 (tx<4, j even); stgt at cols 16..23 (tx 4..5)
            if (tx < 4) {
                if (rlo < N_NODES) mssrc = fmaxf(mssrc, fmaxf(lo0, lo2));
                if (rhi < N_NODES) mssrc = fmaxf(mssrc, fmaxf(hi0, hi2));
            } else if (tx < 6) {
                if (rlo < N_NODES) mstgt = fmaxf(mstgt, fmaxf(fmaxf(lo0, lo1), fmaxf(lo2, lo3)));
                if (rhi < N_NODES) mstgt = fmaxf(mstgt, fmaxf(fmaxf(hi0, hi1), fmaxf(hi2, hi3)));
            }
        }
    }
    if (scal) {
#pragma unroll
        for (int o = 16; o; o >>= 1) {
            mssrc = fmaxf(mssrc, __shfl_xor_sync(0xFFFFFFFFu, mssrc, o));
            mstgt = fmaxf(mstgt, __shfl_xor_sync(0xFFFFFFFFu, mstgt, o));
        }
        if ((tid & 31) == 0) {
            atomicMax(&g_maxraw[0], encodef(mssrc));
            atomicMax(&g_maxraw[1], encodef(mstgt));
        }
    }
}

// ---------------- fused agg (R8 shape): warp/node, 8 nodes/block; paired (ssrc,q) loads ----------------
__global__ void __launch_bounds__(256, 3) k_agg(const float* __restrict__ fpw,
                                                const float* __restrict__ fpb,
                                                const float* __restrict__ gateb,
                                                const float* __restrict__ fbias,
                                                float* __restrict__ out) {
    __shared__ float tdr[50 * NH];
    __shared__ float tda[4 * NH];
    __shared__ float cat_s[8][8][64];
    __shared__ float gate_s[8][8];
    int tid = threadIdx.x, lane = tid & 31, w = tid >> 5;
    for (int i = tid; i < 50 * NH; i += 256) tdr[i] = g_srel_dr[i];
    if (tid < 32) tda[tid] = g_srel_da[tid];
    __syncthreads();

    int n = blockIdx.x * 8 + w;
    float maxssrc = decodef(g_maxraw[0]);
    float maxstgt = decodef(g_maxraw[1]);
    float Mv = leaky(maxssrc + maxstgt);
    float Mr = leaky(g_tabmax[0] + g_tabmax[1] + maxstgt);

    int h = lane >> 2;
    int q4 = lane & 3;
    int e0 = g_off[n], e1 = g_off[n + 1];
    float stgt = g_scal[n * 32 + 16 + h];

    u64 accv2[4], accr2[4];
#pragma unroll
    for (int j = 0; j < 4; j++) { accv2[j] = 0ull; accr2[j] = 0ull; }
    float denv = 0.f, denr = 0.f, accq = 0.f;

    const float* vbase = g_value + h * 32 + q4 * 8;

    int pk = 0;
    float2 SQ = make_float2(0.f, 0.f);
    ulonglong2 X0, X1;
    if (e0 < e1) {
        pk = g_esort[e0];
        int src = pk & 0xFFFF;
        SQ = *(const float2*)(g_scal + src * 32 + 2 * h);
        X0 = *(const ulonglong2*)(vbase + (size_t)src * 256);
        X1 = *(const ulonglong2*)(vbase + (size_t)src * 256 + 4);
    }
    for (int p = e0; p < e1; p++) {
        int pkn = (p + 1 < e1) ? g_esort[p + 1] : pk;
        int srcn = pkn & 0xFFFF;
        float2 SQn = *(const float2*)(g_scal + srcn * 32 + 2 * h);
        ulonglong2 X0n = *(const ulonglong2*)(vbase + (size_t)srcn * 256);
        ulonglong2 X1n = *(const ulonglong2*)(vbase + (size_t)srcn * 256 + 4);

        int dr = (pk >> 16) & 0x3F;
        int da = (pk >> 22) & 0x3;
        float ev = __expf(leaky(SQ.x + stgt) - Mv);
        float er = __expf(leaky(tdr[dr * 8 + h] + tda[da * 8 + h] + stgt) - Mr);
        denv += ev;
        denr += er;
        accq += SQ.y;
        u64 ev2 = bcast2(ev), er2 = bcast2(er);
        ffma2(accv2[0], X0.x, ev2); ffma2(accv2[1], X0.y, ev2);
        ffma2(accv2[2], X1.x, ev2); ffma2(accv2[3], X1.y, ev2);
        ffma2(accr2[0], X0.x, er2); ffma2(accr2[1], X0.y, er2);
        ffma2(accr2[2], X1.x, er2); ffma2(accr2[3], X1.y, er2);

        pk = pkn; SQ = SQn; X0 = X0n; X1 = X1n;
    }

    float idv = 1.f / (denv + EPS);
    float idr = 1.f / (denr + EPS);
    {
        float f0, f1, f2, f3, f4, f5, f6, f7;
        unpack2(accv2[0], f0, f1); unpack2(accv2[1], f2, f3);
        unpack2(accv2[2], f4, f5); unpack2(accv2[3], f6, f7);
        *(float4*)&cat_s[w][h][q4 * 8] = make_float4(f0 * idv, f1 * idv, f2 * idv, f3 * idv);
        *(float4*)&cat_s[w][h][q4 * 8 + 4] = make_float4(f4 * idv, f5 * idv, f6 * idv, f7 * idv);
        unpack2(accr2[0], f0, f1); unpack2(accr2[1], f2, f3);
        unpack2(accr2[2], f4, f5); unpack2(accr2[3], f6, f7);
        *(float4*)&cat_s[w][h][32 + q4 * 8] = make_float4(f0 * idr, f1 * idr, f2 * idr, f3 * idr);
        *(float4*)&cat_s[w][h][32 + q4 * 8 + 4] = make_float4(f4 * idr, f5 * idr, f6 * idr, f7 * idr);
    }

    int deg = e1 - e0;
    if (q4 == 0) {
        float g1 = g_scal[n * 32 + 24 + h];
        float nbterm = deg > 0 ? accq / (float)deg + g_cq[h] : 0.f;
        gate_s[w][h] = 1.f / (1.f + __expf(-(g1 + nbterm + gateb[h])));
    }
    __syncthreads();

    // ---- epilogue: warp w == head hh; two half-passes over d keep regs low ----
    int hh = w;
    float ho[8];
    float bias = fpb[hh * 32 + lane];
#pragma unroll
    for (int nn = 0; nn < 8; nn++) ho[nn] = bias;
#pragma unroll
    for (int half = 0; half < 2; half++) {
        float wreg[32];
#pragma unroll
        for (int d = 0; d < 32; d++) wreg[d] = fpw[hh * 2048 + (half * 32 + d) * 32 + lane];
#pragma unroll
        for (int nn = 0; nn < 8; nn++) {
            float s = 0.f;
#pragma unroll
            for (int d4 = 0; d4 < 8; d4++) {
                float4 c4 = *(const float4*)&cat_s[nn][hh][half * 32 + d4 * 4];
                s += c4.x * wreg[d4 * 4 + 0] + c4.y * wreg[d4 * 4 + 1] +
                     c4.z * wreg[d4 * 4 + 2] + c4.w * wreg[d4 * 4 + 3];
            }
            ho[nn] += s;
        }
    }
    float fb = fbias[hh * 32 + lane];
    int nbase = blockIdx.x * 8;
#pragma unroll
    for (int nn = 0; nn < 8; nn++) {
        out[(size_t)(nbase + nn) * 256 + hh * 32 + lane] = ho[nn] * gate_s[nn][hh] + fb;
    }

    // ---- re-zero CSR state for the next call ----
    if (tid < 8) {
        g_deg[nbase + tid] = 0;
        g_cursor[nbase + tid] = 0;
    }
}

// ---------------- launcher ----------------
extern "C" void kernel_launch(void* const* d_in, const int* in_sizes, int n_in,
                              void* d_out, int out_size) {
    const float* inp = (const float*)d_in[0];
    const float* Wv = (const float*)d_in[2];
    const float* Wrel = (const float*)d_in[3];
    const float* dre_emb = (const float*)d_in[4];
    const float* dae_emb = (const float*)d_in[5];
    const float* wsrc = (const float*)d_in[6];
    const float* wtgt = (const float*)d_in[7];
    const float* wrel = (const float*)d_in[8];
    const float* fpw = (const float*)d_in[9];
    const float* fpb = (const float*)d_in[10];
    const float* Wn = (const float*)d_in[11];
    const float* nbias = (const float*)d_in[12];
    const float* gatew = (const float*)d_in[13];
    const float* gateb = (const float*)d_in[14];
    const float* fbias = (const float*)d_in[15];
    const int* ei = (const int*)d_in[16];
    const int* dre = (const int*)d_in[17];
    const int* dae = (const int*)d_in[18];
    float* out = (float*)d_out;

    k_pre<<<882, 256>>>(Wrel, wrel, dre_emb, dae_emb, Wv, wsrc, wtgt, gatew,
                        Wn, nbias, ei);                                              // 1
    k_scan<<<1, 1024>>>();                                                           // 2
    k_gemm<<<dim3(6, (N_NODES + BM - 1) / BM), 256>>>(inp, Wv, ei, dre, dae);        // 3
    k_agg<<<2500, 256>>>(fpw, fpb, gateb, fbias, out);                               // 4 (profiled)
}